// round 7
// baseline (speedup 1.0000x reference)
#include <cuda_runtime.h>
#include <cstdint>

// Problem constants
constexpr int B    = 512;
constexpr int T    = 512;
constexpr int F_IN = 8;
constexpr int H    = 128;
constexpr int NG   = 4 * H;   // 512
constexpr int OUTD = 7;

// Scan kernel config
constexpr int BB  = 4;            // batch rows per CTA
constexpr int WKS = 112;          // k-rows of W_hh kept in smem
constexpr int WKR = H - WKS;      // 16 k-rows kept in registers
constexpr int SCAN_THREADS = H;   // one thread per hidden unit j
constexpr int SCAN_SMEM = (WKS * NG + H * BB) * 4;  // 229376 + 2048 = 231424 B

// Scratch buffers (static __device__ — no allocation in kernel_launch)
constexpr size_t XG_ELEMS   = (size_t)T * B * NG;   // 134,217,728 floats
constexpr size_t HBUF_ELEMS = (size_t)T * B * H;    // 33,554,432 floats

__device__ float g_xg[XG_ELEMS];
__device__ float g_h0[HBUF_ELEMS];
__device__ float g_h1[HBUF_ELEMS];
__device__ float g_Wp[3][H * NG];    // permuted W_hh: [k][j][gate]
__device__ float g_bias[3][NG];      // b_ih + b_hh combined

// ---------------------------------------------------------------------------
// f32x2 packed math helpers (Blackwell fma.rn.f32x2)
// ---------------------------------------------------------------------------
__device__ __forceinline__ unsigned long long pack2(float lo, float hi) {
    unsigned long long r;
    asm("mov.b64 %0, {%1, %2};" : "=l"(r) : "f"(lo), "f"(hi));
    return r;
}
__device__ __forceinline__ float2 unpack2(unsigned long long v) {
    float2 r;
    asm("mov.b64 {%0, %1}, %2;" : "=f"(r.x), "=f"(r.y) : "l"(v));
    return r;
}
__device__ __forceinline__ void fma2(unsigned long long& d, unsigned long long a,
                                     unsigned long long b) {
    asm("fma.rn.f32x2 %0, %1, %2, %0;" : "+l"(d) : "l"(a), "l"(b));
}

__device__ __forceinline__ float sigmoidf_(float x) {
    return __fdividef(1.f, 1.f + __expf(-x));
}
__device__ __forceinline__ float tanhf_(float x) {
    float ax = fabsf(x);
    float e  = __expf(-2.f * ax);
    float r  = __fdividef(1.f - e, 1.f + e);
    return x < 0.f ? -r : r;
}

// ---------------------------------------------------------------------------
// prep: permute W_hh into [k][j][gate] layout; combine biases
// ---------------------------------------------------------------------------
__global__ void prep_kernel(const float* __restrict__ whh,
                            const float* __restrict__ bih,
                            const float* __restrict__ bhh,
                            float* __restrict__ Wp,
                            float* __restrict__ bias) {
    int i = blockIdx.x * blockDim.x + threadIdx.x;
    if (i < H * NG) {
        int g = i & 3;
        int j = (i >> 2) & (H - 1);
        int k = i >> 9;
        Wp[i] = whh[(g * H + j) * H + k];
    }
    if (i < NG) bias[i] = bih[i] + bhh[i];
}

// ---------------------------------------------------------------------------
// proj0: layer-0 input projection (K = 8)
// xg[m][n] = bias[n] + sum_f x[b][t][f] * wih[n][f],  m = t*B + b
// ---------------------------------------------------------------------------
constexpr int P0_ROWS = 16;
__global__ __launch_bounds__(256) void proj0_kernel(const float* __restrict__ x,
                                                    const float* __restrict__ wih,
                                                    const float* __restrict__ bias,
                                                    float* __restrict__ xg) {
    __shared__ float ws[NG * F_IN];
    __shared__ float bs[NG];
    __shared__ float xs[P0_ROWS][F_IN];
    const int tid = threadIdx.x;
    for (int i = tid; i < NG * F_IN; i += 256) ws[i] = wih[i];
    for (int i = tid; i < NG; i += 256) bs[i] = bias[i];
    const int m0 = blockIdx.x * P0_ROWS;
    if (tid < P0_ROWS * F_IN) {
        int r = tid / F_IN, f = tid % F_IN;
        int m = m0 + r;
        int t = m / B, b = m % B;
        xs[r][f] = x[((size_t)b * T + t) * F_IN + f];
    }
    __syncthreads();

    float wv[2][F_IN];
    float bv[2];
#pragma unroll
    for (int q = 0; q < 2; q++) {
        int n = tid + q * 256;
        bv[q] = bs[n];
#pragma unroll
        for (int f = 0; f < F_IN; f++) wv[q][f] = ws[n * F_IN + f];
    }
    for (int r = 0; r < P0_ROWS; r++) {
        float xv[F_IN];
#pragma unroll
        for (int f = 0; f < F_IN; f++) xv[f] = xs[r][f];
#pragma unroll
        for (int q = 0; q < 2; q++) {
            float acc = bv[q];
#pragma unroll
            for (int f = 0; f < F_IN; f++) acc += xv[f] * wv[q][f];
            xg[(size_t)(m0 + r) * NG + tid + q * 256] = acc;
        }
    }
}

// ---------------------------------------------------------------------------
// gemm_proj: input projection for layers 1,2.
// C[m][n] = bias[n] + sum_k A[m][k] * W[n][k]
// M = T*B, N = 512, K = 128. 128x128 tile, BK=16, 256 threads, 8x8/thread,
// f32x2 packed microkernel.
// ---------------------------------------------------------------------------
constexpr int GBM = 128, GBN = 128, GBK = 16;
__global__ __launch_bounds__(256, 2) void gemm_proj(const float* __restrict__ A,
                                                    const float* __restrict__ W,
                                                    const float* __restrict__ bias,
                                                    float* __restrict__ C) {
    __shared__ float As[GBK][GBM];
    __shared__ float Ws[GBK][GBN];
    const int tid = threadIdx.x;
    const int tx = tid & 15, ty = tid >> 4;
    const int m0 = blockIdx.x * GBM, n0 = blockIdx.y * GBN;
    const int lr = tid >> 2;
    const int lc = (tid & 3) << 2;

    unsigned long long acc[8][4];
#pragma unroll
    for (int i = 0; i < 8; i++)
#pragma unroll
        for (int j = 0; j < 4; j++) acc[i][j] = 0ull;

    for (int k0 = 0; k0 < H; k0 += GBK) {
        if (k0) __syncthreads();
#pragma unroll
        for (int i = 0; i < 2; i++) {
            int r = lr + (i << 6);
            float4 av = *(const float4*)(A + (size_t)(m0 + r) * H + k0 + lc);
            As[lc + 0][r] = av.x; As[lc + 1][r] = av.y;
            As[lc + 2][r] = av.z; As[lc + 3][r] = av.w;
            float4 wv = *(const float4*)(W + (size_t)(n0 + r) * H + k0 + lc);
            Ws[lc + 0][r] = wv.x; Ws[lc + 1][r] = wv.y;
            Ws[lc + 2][r] = wv.z; Ws[lc + 3][r] = wv.w;
        }
        __syncthreads();
#pragma unroll
        for (int k = 0; k < GBK; k++) {
            float a[8];
            *(float4*)(a)     = *(const float4*)&As[k][ty * 8];
            *(float4*)(a + 4) = *(const float4*)&As[k][ty * 8 + 4];
            // b operand pairs straight from smem (contiguous n pairs)
            const ulonglong2* bp = (const ulonglong2*)&Ws[k][tx * 8];
            ulonglong2 b01 = bp[0];
            ulonglong2 b23 = bp[1];
#pragma unroll
            for (int i = 0; i < 8; i++) {
                unsigned long long ai = pack2(a[i], a[i]);
                fma2(acc[i][0], ai, b01.x);
                fma2(acc[i][1], ai, b01.y);
                fma2(acc[i][2], ai, b23.x);
                fma2(acc[i][3], ai, b23.y);
            }
        }
    }

    float bb[8];
    *(float4*)(bb)     = *(const float4*)(bias + n0 + tx * 8);
    *(float4*)(bb + 4) = *(const float4*)(bias + n0 + tx * 8 + 4);
#pragma unroll
    for (int i = 0; i < 8; i++) {
        float o[8];
#pragma unroll
        for (int j = 0; j < 4; j++) {
            float2 v = unpack2(acc[i][j]);
            o[2 * j]     = v.x + bb[2 * j];
            o[2 * j + 1] = v.y + bb[2 * j + 1];
        }
        size_t row = (size_t)(m0 + ty * 8 + i) * NG + n0 + tx * 8;
        *(float4*)(C + row)     = *(float4*)(o);
        *(float4*)(C + row + 4) = *(float4*)(o + 4);
    }
}

// ---------------------------------------------------------------------------
// lstm_scan: the sequential recurrence for one layer.
// 128 CTAs x 4 batch rows. W_hh resident: k<112 in smem, k>=112 in registers.
// One thread per hidden unit j; f32x2 packed FMAs over gate pairs.
// ---------------------------------------------------------------------------
extern __shared__ float s_mem[];
__global__ __launch_bounds__(SCAN_THREADS) void lstm_scan(const float* __restrict__ xg,
                                                          const float* __restrict__ Wp,
                                                          float* __restrict__ hout) {
    float* Wsm = s_mem;                  // [WKS][128][4]
    float* hsm = s_mem + WKS * NG;       // [H][BB]
    const int j  = threadIdx.x;
    const int b0 = blockIdx.x * BB;

    // Load weight body into smem
    {
        const float4* src = (const float4*)Wp;
        float4* dst = (float4*)Wsm;
        for (int i = j; i < WKS * NG / 4; i += SCAN_THREADS) dst[i] = src[i];
    }
    // Weight tail into registers: wreg[kk] = W[(WKS+kk)][j][0..3]
    float4 wreg[WKR];
    {
        const float4* src = (const float4*)Wp;
#pragma unroll
        for (int kk = 0; kk < WKR; kk++) wreg[kk] = src[(WKS + kk) * H + j];
    }
    ((float4*)hsm)[j] = make_float4(0.f, 0.f, 0.f, 0.f);
    float c[BB] = {0.f, 0.f, 0.f, 0.f};
    __syncthreads();

    const ulonglong2* Wsm2 = (const ulonglong2*)Wsm;
    const float4* hsm4 = (const float4*)hsm;

    for (int t = 0; t < T; t++) {
        // Issue xg loads early (DRAM latency hidden under the k-loop)
        float xgv[BB][4];
#pragma unroll
        for (int b = 0; b < BB; b++) {
            const float* p = xg + ((size_t)t * B + (b0 + b)) * NG + j;
#pragma unroll
            for (int g = 0; g < 4; g++) xgv[b][g] = __ldg(p + g * H);
        }

        unsigned long long a0[BB], a1[BB];   // (i,f) and (g,o) accumulators
#pragma unroll
        for (int b = 0; b < BB; b++) { a0[b] = 0ull; a1[b] = 0ull; }

#pragma unroll 8
        for (int k = 0; k < WKS; k++) {
            ulonglong2 wp = Wsm2[k * H + j];   // lo: (w_i, w_f), hi: (w_g, w_o)
            float4 hv = hsm4[k];               // h[b0..b3][k], broadcast
            unsigned long long h0 = pack2(hv.x, hv.x);
            unsigned long long h1 = pack2(hv.y, hv.y);
            unsigned long long h2 = pack2(hv.z, hv.z);
            unsigned long long h3 = pack2(hv.w, hv.w);
            fma2(a0[0], h0, wp.x); fma2(a1[0], h0, wp.y);
            fma2(a0[1], h1, wp.x); fma2(a1[1], h1, wp.y);
            fma2(a0[2], h2, wp.x); fma2(a1[2], h2, wp.y);
            fma2(a0[3], h3, wp.x); fma2(a1[3], h3, wp.y);
        }
#pragma unroll
        for (int kk = 0; kk < WKR; kk++) {
            float4 w = wreg[kk];
            unsigned long long w01 = pack2(w.x, w.y);
            unsigned long long w23 = pack2(w.z, w.w);
            float4 hv = hsm4[WKS + kk];
            unsigned long long h0 = pack2(hv.x, hv.x);
            unsigned long long h1 = pack2(hv.y, hv.y);
            unsigned long long h2 = pack2(hv.z, hv.z);
            unsigned long long h3 = pack2(hv.w, hv.w);
            fma2(a0[0], h0, w01); fma2(a1[0], h0, w23);
            fma2(a0[1], h1, w01); fma2(a1[1], h1, w23);
            fma2(a0[2], h2, w01); fma2(a1[2], h2, w23);
            fma2(a0[3], h3, w01); fma2(a1[3], h3, w23);
        }

        float hnew[BB];
#pragma unroll
        for (int b = 0; b < BB; b++) {
            float2 v0 = unpack2(a0[b]);
            float2 v1 = unpack2(a1[b]);
            float gi = sigmoidf_(v0.x + xgv[b][0]);
            float gf = sigmoidf_(v0.y + xgv[b][1]);
            float gg = tanhf_(v1.x + xgv[b][2]);
            float go = sigmoidf_(v1.y + xgv[b][3]);
            float cb = gf * c[b] + gi * gg;
            c[b] = cb;
            hnew[b] = go * tanhf_(cb);
        }

        __syncthreads();  // all reads of old h done
        ((float4*)hsm)[j] = make_float4(hnew[0], hnew[1], hnew[2], hnew[3]);
#pragma unroll
        for (int b = 0; b < BB; b++)
            hout[((size_t)t * B + (b0 + b)) * H + j] = hnew[b];
        __syncthreads();  // new h visible
    }
}

// ---------------------------------------------------------------------------
// fc_head: y = relu(h_last @ fc1^T + b1) @ fc2^T + b2
// ---------------------------------------------------------------------------
__global__ __launch_bounds__(H) void fc_head(const float* __restrict__ hlast,
                                             const float* __restrict__ w1,
                                             const float* __restrict__ b1,
                                             const float* __restrict__ w2,
                                             const float* __restrict__ b2,
                                             float* __restrict__ out) {
    __shared__ float hs[H];
    __shared__ float ys[H];
    const int b = blockIdx.x, i = threadIdx.x;
    hs[i] = hlast[(size_t)b * H + i];
    __syncthreads();
    float acc = b1[i];
    const float* wr = w1 + i * H;
#pragma unroll 8
    for (int k = 0; k < H; k++) acc += hs[k] * wr[k];
    ys[i] = fmaxf(acc, 0.f);
    __syncthreads();
    if (i < OUTD) {
        float a = b2[i];
        const float* w2r = w2 + i * H;
#pragma unroll 8
        for (int k = 0; k < H; k++) a += ys[k] * w2r[k];
        out[(size_t)b * OUTD + i] = a;
    }
}

// ---------------------------------------------------------------------------
// kernel_launch
// inputs: x, (w_ih,w_hh,b_ih,b_hh) x3, fc1_w, fc1_b, fc2_w, fc2_b
// ---------------------------------------------------------------------------
extern "C" void kernel_launch(void* const* d_in, const int* in_sizes, int n_in,
                              void* d_out, int out_size) {
    const float* x = (const float*)d_in[0];
    const float* wih[3] = {(const float*)d_in[1], (const float*)d_in[5], (const float*)d_in[9]};
    const float* whh[3] = {(const float*)d_in[2], (const float*)d_in[6], (const float*)d_in[10]};
    const float* bih[3] = {(const float*)d_in[3], (const float*)d_in[7], (const float*)d_in[11]};
    const float* bhh[3] = {(const float*)d_in[4], (const float*)d_in[8], (const float*)d_in[12]};
    const float* fc1w = (const float*)d_in[13];
    const float* fc1b = (const float*)d_in[14];
    const float* fc2w = (const float*)d_in[15];
    const float* fc2b = (const float*)d_in[16];
    float* out = (float*)d_out;

    float *xg, *h0, *h1, *Wp, *bias;
    cudaGetSymbolAddress((void**)&xg, g_xg);
    cudaGetSymbolAddress((void**)&h0, g_h0);
    cudaGetSymbolAddress((void**)&h1, g_h1);
    cudaGetSymbolAddress((void**)&Wp, g_Wp);
    cudaGetSymbolAddress((void**)&bias, g_bias);

    cudaFuncSetAttribute(lstm_scan, cudaFuncAttributeMaxDynamicSharedMemorySize, SCAN_SMEM);

    // 1) weight permute + bias combine (3 layers)
    for (int l = 0; l < 3; l++)
        prep_kernel<<<(H * NG + 255) / 256, 256>>>(whh[l], bih[l], bhh[l],
                                                   Wp + (size_t)l * H * NG,
                                                   bias + (size_t)l * NG);

    // 2) layer 0 input projection
    proj0_kernel<<<(T * B) / P0_ROWS, 256>>>(x, wih[0], bias, xg);

    // 3) layer 0 scan
    lstm_scan<<<B / BB, SCAN_THREADS, SCAN_SMEM>>>(xg, Wp, h0);

    // 4) layer 1 projection + scan
    {
        dim3 grid((T * B) / GBM, NG / GBN);
        gemm_proj<<<grid, 256>>>(h0, wih[1], bias + NG, xg);
    }
    lstm_scan<<<B / BB, SCAN_THREADS, SCAN_SMEM>>>(xg, Wp + (size_t)H * NG, h1);

    // 5) layer 2 projection + scan
    {
        dim3 grid((T * B) / GBM, NG / GBN);
        gemm_proj<<<grid, 256>>>(h1, wih[2], bias + 2 * NG, xg);
    }
    lstm_scan<<<B / BB, SCAN_THREADS, SCAN_SMEM>>>(xg, Wp + (size_t)2 * H * NG, h0);

    // 6) FC head on h[T-1] of layer 2
    fc_head<<<B, H>>>(h0 + (size_t)(T - 1) * B * H, fc1w, fc1b, fc2w, fc2b, out);
}

// round 15
// speedup vs baseline: 1.0977x; 1.0977x over previous
#include <cuda_runtime.h>
#include <cstdint>

// Problem constants
constexpr int B    = 512;
constexpr int T    = 512;
constexpr int F_IN = 8;
constexpr int H    = 128;
constexpr int NG   = 4 * H;   // 512
constexpr int OUTD = 7;

// Scan kernel config
constexpr int BB  = 4;            // batch rows per CTA
constexpr int WKS = 96;           // k-rows of W_hh kept in smem
constexpr int WKR = H - WKS;      // 32 k-rows kept in registers
constexpr int SCAN_THREADS = H;   // one thread per hidden unit j
// W body + double-buffered h: 96*512*4 + 2*512*4 = 196608 + 4096 = 200704 B
constexpr int SCAN_SMEM = (WKS * NG + 2 * H * BB) * 4;

// Scratch buffers (static __device__ — no allocation in kernel_launch)
constexpr size_t XG_ELEMS   = (size_t)T * B * NG;   // 134,217,728 floats
constexpr size_t HBUF_ELEMS = (size_t)T * B * H;    // 33,554,432 floats

__device__ float g_xg[XG_ELEMS];
__device__ float g_h0[HBUF_ELEMS];
__device__ float g_h1[HBUF_ELEMS];
__device__ float g_Wp[3][H * NG];    // permuted W_hh: [k][j][gate]
__device__ float g_bias[3][NG];      // b_ih + b_hh combined

// ---------------------------------------------------------------------------
// f32x2 packed math helpers (Blackwell fma.rn.f32x2)
// ---------------------------------------------------------------------------
__device__ __forceinline__ unsigned long long pack2(float lo, float hi) {
    unsigned long long r;
    asm("mov.b64 %0, {%1, %2};" : "=l"(r) : "f"(lo), "f"(hi));
    return r;
}
__device__ __forceinline__ float2 unpack2(unsigned long long v) {
    float2 r;
    asm("mov.b64 {%0, %1}, %2;" : "=f"(r.x), "=f"(r.y) : "l"(v));
    return r;
}
__device__ __forceinline__ void fma2(unsigned long long& d, unsigned long long a,
                                     unsigned long long b) {
    asm("fma.rn.f32x2 %0, %1, %2, %0;" : "+l"(d) : "l"(a), "l"(b));
}

__device__ __forceinline__ float sigmoidf_(float x) {
    return __fdividef(1.f, 1.f + __expf(-x));
}
__device__ __forceinline__ float tanhf_(float x) {
    float ax = fabsf(x);
    float e  = __expf(-2.f * ax);
    float r  = __fdividef(1.f - e, 1.f + e);
    return x < 0.f ? -r : r;
}

// ---------------------------------------------------------------------------
// prep: permute W_hh into [k][j][gate] layout; combine biases
// ---------------------------------------------------------------------------
__global__ void prep_kernel(const float* __restrict__ whh,
                            const float* __restrict__ bih,
                            const float* __restrict__ bhh,
                            float* __restrict__ Wp,
                            float* __restrict__ bias) {
    int i = blockIdx.x * blockDim.x + threadIdx.x;
    if (i < H * NG) {
        int g = i & 3;
        int j = (i >> 2) & (H - 1);
        int k = i >> 9;
        Wp[i] = whh[(g * H + j) * H + k];
    }
    if (i < NG) bias[i] = bih[i] + bhh[i];
}

// ---------------------------------------------------------------------------
// proj0: layer-0 input projection (K = 8)
// ---------------------------------------------------------------------------
constexpr int P0_ROWS = 16;
__global__ __launch_bounds__(256) void proj0_kernel(const float* __restrict__ x,
                                                    const float* __restrict__ wih,
                                                    const float* __restrict__ bias,
                                                    float* __restrict__ xg) {
    __shared__ float ws[NG * F_IN];
    __shared__ float bs[NG];
    __shared__ float xs[P0_ROWS][F_IN];
    const int tid = threadIdx.x;
    for (int i = tid; i < NG * F_IN; i += 256) ws[i] = wih[i];
    for (int i = tid; i < NG; i += 256) bs[i] = bias[i];
    const int m0 = blockIdx.x * P0_ROWS;
    if (tid < P0_ROWS * F_IN) {
        int r = tid / F_IN, f = tid % F_IN;
        int m = m0 + r;
        int t = m / B, b = m % B;
        xs[r][f] = x[((size_t)b * T + t) * F_IN + f];
    }
    __syncthreads();

    float wv[2][F_IN];
    float bv[2];
#pragma unroll
    for (int q = 0; q < 2; q++) {
        int n = tid + q * 256;
        bv[q] = bs[n];
#pragma unroll
        for (int f = 0; f < F_IN; f++) wv[q][f] = ws[n * F_IN + f];
    }
    for (int r = 0; r < P0_ROWS; r++) {
        float xv[F_IN];
#pragma unroll
        for (int f = 0; f < F_IN; f++) xv[f] = xs[r][f];
#pragma unroll
        for (int q = 0; q < 2; q++) {
            float acc = bv[q];
#pragma unroll
            for (int f = 0; f < F_IN; f++) acc += xv[f] * wv[q][f];
            xg[(size_t)(m0 + r) * NG + tid + q * 256] = acc;
        }
    }
}

// ---------------------------------------------------------------------------
// gemm_proj: input projection for layers 1,2
// ---------------------------------------------------------------------------
constexpr int GBM = 128, GBN = 128, GBK = 16;
__global__ __launch_bounds__(256, 2) void gemm_proj(const float* __restrict__ A,
                                                    const float* __restrict__ W,
                                                    const float* __restrict__ bias,
                                                    float* __restrict__ C) {
    __shared__ float As[GBK][GBM];
    __shared__ float Ws[GBK][GBN];
    const int tid = threadIdx.x;
    const int tx = tid & 15, ty = tid >> 4;
    const int m0 = blockIdx.x * GBM, n0 = blockIdx.y * GBN;
    const int lr = tid >> 2;
    const int lc = (tid & 3) << 2;

    unsigned long long acc[8][4];
#pragma unroll
    for (int i = 0; i < 8; i++)
#pragma unroll
        for (int j = 0; j < 4; j++) acc[i][j] = 0ull;

    for (int k0 = 0; k0 < H; k0 += GBK) {
        if (k0) __syncthreads();
#pragma unroll
        for (int i = 0; i < 2; i++) {
            int r = lr + (i << 6);
            float4 av = *(const float4*)(A + (size_t)(m0 + r) * H + k0 + lc);
            As[lc + 0][r] = av.x; As[lc + 1][r] = av.y;
            As[lc + 2][r] = av.z; As[lc + 3][r] = av.w;
            float4 wv = *(const float4*)(W + (size_t)(n0 + r) * H + k0 + lc);
            Ws[lc + 0][r] = wv.x; Ws[lc + 1][r] = wv.y;
            Ws[lc + 2][r] = wv.z; Ws[lc + 3][r] = wv.w;
        }
        __syncthreads();
#pragma unroll
        for (int k = 0; k < GBK; k++) {
            float a[8];
            *(float4*)(a)     = *(const float4*)&As[k][ty * 8];
            *(float4*)(a + 4) = *(const float4*)&As[k][ty * 8 + 4];
            const ulonglong2* bp = (const ulonglong2*)&Ws[k][tx * 8];
            ulonglong2 b01 = bp[0];
            ulonglong2 b23 = bp[1];
#pragma unroll
            for (int i = 0; i < 8; i++) {
                unsigned long long ai = pack2(a[i], a[i]);
                fma2(acc[i][0], ai, b01.x);
                fma2(acc[i][1], ai, b01.y);
                fma2(acc[i][2], ai, b23.x);
                fma2(acc[i][3], ai, b23.y);
            }
        }
    }

    float bb[8];
    *(float4*)(bb)     = *(const float4*)(bias + n0 + tx * 8);
    *(float4*)(bb + 4) = *(const float4*)(bias + n0 + tx * 8 + 4);
#pragma unroll
    for (int i = 0; i < 8; i++) {
        float o[8];
#pragma unroll
        for (int j = 0; j < 4; j++) {
            float2 v = unpack2(acc[i][j]);
            o[2 * j]     = v.x + bb[2 * j];
            o[2 * j + 1] = v.y + bb[2 * j + 1];
        }
        size_t row = (size_t)(m0 + ty * 8 + i) * NG + n0 + tx * 8;
        *(float4*)(C + row)     = *(float4*)(o);
        *(float4*)(C + row + 4) = *(float4*)(o + 4);
    }
}

// ---------------------------------------------------------------------------
// lstm_scan: sequential recurrence, one layer.
// 128 CTAs x 4 batch rows. W_hh: k<96 in smem, k>=96 in registers (128 regs).
// Double-buffered h in smem -> ONE __syncthreads per step.
// ---------------------------------------------------------------------------
extern __shared__ float s_mem[];
__global__ __launch_bounds__(SCAN_THREADS) void lstm_scan(const float* __restrict__ xg,
                                                          const float* __restrict__ Wp,
                                                          float* __restrict__ hout) {
    float* Wsm  = s_mem;                   // [WKS][128][4]
    float* hsmA = s_mem + WKS * NG;        // h buffer 0: [H][BB]
    float* hsmB = hsmA + H * BB;           // h buffer 1
    const int j  = threadIdx.x;
    const int b0 = blockIdx.x * BB;

    // Load weight body into smem
    {
        const float4* src = (const float4*)Wp;
        float4* dst = (float4*)Wsm;
        for (int i = j; i < WKS * NG / 4; i += SCAN_THREADS) dst[i] = src[i];
    }
    // Weight tail into registers: wreg[kk] = W[(WKS+kk)][j][0..3]
    float4 wreg[WKR];
    {
        const float4* src = (const float4*)Wp;
#pragma unroll
        for (int kk = 0; kk < WKR; kk++) wreg[kk] = src[(WKS + kk) * H + j];
    }
    ((float4*)hsmA)[j] = make_float4(0.f, 0.f, 0.f, 0.f);
    float c[BB] = {0.f, 0.f, 0.f, 0.f};
    __syncthreads();

    const ulonglong2* Wsm2 = (const ulonglong2*)Wsm;

    for (int t = 0; t < T; t++) {
        const float4* hr = (const float4*)((t & 1) ? hsmB : hsmA);  // read buf
        float4*       hw = (float4*)((t & 1) ? hsmA : hsmB);        // write buf

        // Issue xg loads early (DRAM latency hidden under the k-loop)
        float xgv[BB][4];
#pragma unroll
        for (int b = 0; b < BB; b++) {
            const float* p = xg + ((size_t)t * B + (b0 + b)) * NG + j;
#pragma unroll
            for (int g = 0; g < 4; g++) xgv[b][g] = __ldg(p + g * H);
        }

        unsigned long long a0[BB], a1[BB];   // (i,f) and (g,o) accumulators
#pragma unroll
        for (int b = 0; b < BB; b++) { a0[b] = 0ull; a1[b] = 0ull; }

#pragma unroll 8
        for (int k = 0; k < WKS; k++) {
            ulonglong2 wp = Wsm2[k * H + j];   // lo: (w_i, w_f), hi: (w_g, w_o)
            float4 hv = hr[k];                 // h[b0..b3][k], broadcast
            unsigned long long h0 = pack2(hv.x, hv.x);
            unsigned long long h1 = pack2(hv.y, hv.y);
            unsigned long long h2 = pack2(hv.z, hv.z);
            unsigned long long h3 = pack2(hv.w, hv.w);
            fma2(a0[0], h0, wp.x); fma2(a1[0], h0, wp.y);
            fma2(a0[1], h1, wp.x); fma2(a1[1], h1, wp.y);
            fma2(a0[2], h2, wp.x); fma2(a1[2], h2, wp.y);
            fma2(a0[3], h3, wp.x); fma2(a1[3], h3, wp.y);
        }
#pragma unroll
        for (int kk = 0; kk < WKR; kk++) {
            float4 w = wreg[kk];
            unsigned long long w01 = pack2(w.x, w.y);
            unsigned long long w23 = pack2(w.z, w.w);
            float4 hv = hr[WKS + kk];
            unsigned long long h0 = pack2(hv.x, hv.x);
            unsigned long long h1 = pack2(hv.y, hv.y);
            unsigned long long h2 = pack2(hv.z, hv.z);
            unsigned long long h3 = pack2(hv.w, hv.w);
            fma2(a0[0], h0, w01); fma2(a1[0], h0, w23);
            fma2(a0[1], h1, w01); fma2(a1[1], h1, w23);
            fma2(a0[2], h2, w01); fma2(a1[2], h2, w23);
            fma2(a0[3], h3, w01); fma2(a1[3], h3, w23);
        }

        float hnew[BB];
#pragma unroll
        for (int b = 0; b < BB; b++) {
            float2 v0 = unpack2(a0[b]);
            float2 v1 = unpack2(a1[b]);
            float gi = sigmoidf_(v0.x + xgv[b][0]);
            float gf = sigmoidf_(v0.y + xgv[b][1]);
            float gg = tanhf_(v1.x + xgv[b][2]);
            float go = sigmoidf_(v1.y + xgv[b][3]);
            float cb = gf * c[b] + gi * gg;
            c[b] = cb;
            hnew[b] = go * tanhf_(cb);
        }

        // Write NEW h to the other buffer — no conflict with this step's reads.
        hw[j] = make_float4(hnew[0], hnew[1], hnew[2], hnew[3]);
#pragma unroll
        for (int b = 0; b < BB; b++)
            hout[((size_t)t * B + (b0 + b)) * H + j] = hnew[b];
        __syncthreads();  // new h visible before next step's reads
    }
}

// ---------------------------------------------------------------------------
// fc_head: y = relu(h_last @ fc1^T + b1) @ fc2^T + b2
// ---------------------------------------------------------------------------
__global__ __launch_bounds__(H) void fc_head(const float* __restrict__ hlast,
                                             const float* __restrict__ w1,
                                             const float* __restrict__ b1,
                                             const float* __restrict__ w2,
                                             const float* __restrict__ b2,
                                             float* __restrict__ out) {
    __shared__ float hs[H];
    __shared__ float ys[H];
    const int b = blockIdx.x, i = threadIdx.x;
    hs[i] = hlast[(size_t)b * H + i];
    __syncthreads();
    float acc = b1[i];
    const float* wr = w1 + i * H;
#pragma unroll 8
    for (int k = 0; k < H; k++) acc += hs[k] * wr[k];
    ys[i] = fmaxf(acc, 0.f);
    __syncthreads();
    if (i < OUTD) {
        float a = b2[i];
        const float* w2r = w2 + i * H;
#pragma unroll 8
        for (int k = 0; k < H; k++) a += ys[k] * w2r[k];
        out[(size_t)b * OUTD + i] = a;
    }
}

// ---------------------------------------------------------------------------
// kernel_launch
// ---------------------------------------------------------------------------
extern "C" void kernel_launch(void* const* d_in, const int* in_sizes, int n_in,
                              void* d_out, int out_size) {
    const float* x = (const float*)d_in[0];
    const float* wih[3] = {(const float*)d_in[1], (const float*)d_in[5], (const float*)d_in[9]};
    const float* whh[3] = {(const float*)d_in[2], (const float*)d_in[6], (const float*)d_in[10]};
    const float* bih[3] = {(const float*)d_in[3], (const float*)d_in[7], (const float*)d_in[11]};
    const float* bhh[3] = {(const float*)d_in[4], (const float*)d_in[8], (const float*)d_in[12]};
    const float* fc1w = (const float*)d_in[13];
    const float* fc1b = (const float*)d_in[14];
    const float* fc2w = (const float*)d_in[15];
    const float* fc2b = (const float*)d_in[16];
    float* out = (float*)d_out;

    float *xg, *h0, *h1, *Wp, *bias;
    cudaGetSymbolAddress((void**)&xg, g_xg);
    cudaGetSymbolAddress((void**)&h0, g_h0);
    cudaGetSymbolAddress((void**)&h1, g_h1);
    cudaGetSymbolAddress((void**)&Wp, g_Wp);
    cudaGetSymbolAddress((void**)&bias, g_bias);

    cudaFuncSetAttribute(lstm_scan, cudaFuncAttributeMaxDynamicSharedMemorySize, SCAN_SMEM);

    // 1) weight permute + bias combine (3 layers)
    for (int l = 0; l < 3; l++)
        prep_kernel<<<(H * NG + 255) / 256, 256>>>(whh[l], bih[l], bhh[l],
                                                   Wp + (size_t)l * H * NG,
                                                   bias + (size_t)l * NG);

    // 2) layer 0 input projection
    proj0_kernel<<<(T * B) / P0_ROWS, 256>>>(x, wih[0], bias, xg);

    // 3) layer 0 scan
    lstm_scan<<<B / BB, SCAN_THREADS, SCAN_SMEM>>>(xg, Wp, h0);

    // 4) layer 1 projection + scan
    {
        dim3 grid((T * B) / GBM, NG / GBN);
        gemm_proj<<<grid, 256>>>(h0, wih[1], bias + NG, xg);
    }
    lstm_scan<<<B / BB, SCAN_THREADS, SCAN_SMEM>>>(xg, Wp + (size_t)H * NG, h1);

    // 5) layer 2 projection + scan
    {
        dim3 grid((T * B) / GBM, NG / GBN);
        gemm_proj<<<grid, 256>>>(h1, wih[2], bias + 2 * NG, xg);
    }
    lstm_scan<<<B / BB, SCAN_THREADS, SCAN_SMEM>>>(xg, Wp + (size_t)2 * H * NG, h0);

    // 6) FC head on h[T-1] of layer 2
    fc_head<<<B, H>>>(h0 + (size_t)(T - 1) * B * H, fc1w, fc1b, fc2w, fc2b, out);
}